// round 1
// baseline (speedup 1.0000x reference)
#include <cuda_runtime.h>

// Problem constants (fixed by the dataset: N1=N2=50000, F=1024, D=128, H1=64, H2=32, E=1e6)
#define FDIM  1024
#define DDIM  128
#define H1DIM 64
#define H2DIM 32
#define NMAX  50000

// Scratch (static device globals — no runtime allocation allowed)
__device__ float g_Wc1[FDIM * H1DIM];   // W1 @ Wm1[:128]   [1024,64]
__device__ float g_Wc2[FDIM * H1DIM];   // W2 @ Wm1[128:]   [1024,64]
__device__ float g_bc1[H1DIM];          // b1@Wm1a + bm1
__device__ float g_bc2[H1DIM];          // b2@Wm1b
__device__ float g_g1[NMAX * H1DIM];    // x_gene @ Wc1 + bc1   [50000,64]
__device__ float g_g2[NMAX * H1DIM];    // x_cell @ Wc2 + bc2   [50000,64]

// ---------------------------------------------------------------------------
// Kernel 1: fold W{1,2} (1024x128) with Wm1 halves (128x64) -> Wc{1,2} (1024x64)
// grid (1024, 2), block 64
// ---------------------------------------------------------------------------
__global__ void fold_weights_kernel(const float* __restrict__ W1,
                                    const float* __restrict__ W2,
                                    const float* __restrict__ Wm1) {
    const int f    = blockIdx.x;
    const int half = blockIdx.y;
    const int j    = threadIdx.x;          // 0..63
    const float* W  = half ? W2 : W1;
    float*       Wc = half ? g_Wc2 : g_Wc1;
    const int off = half * DDIM;
    float acc = 0.f;
#pragma unroll 8
    for (int d = 0; d < DDIM; d++)
        acc = fmaf(W[f * DDIM + d], Wm1[(off + d) * H1DIM + j], acc);
    Wc[f * H1DIM + j] = acc;
}

// Kernel 1b: fold biases. block 128 (64 per half)
__global__ void fold_bias_kernel(const float* __restrict__ b1,
                                 const float* __restrict__ b2,
                                 const float* __restrict__ Wm1,
                                 const float* __restrict__ bm1) {
    const int t = threadIdx.x;
    if (t >= 128) return;
    const int j = t & 63;
    const int half = t >> 6;
    const float* b = half ? b2 : b1;
    const int off = half * DDIM;
    float acc = half ? 0.f : bm1[j];       // bm1 folded once, into the gene side
#pragma unroll 8
    for (int d = 0; d < DDIM; d++)
        acc = fmaf(b[d], Wm1[(off + d) * H1DIM + j], acc);
    (half ? g_bc2 : g_bc1)[j] = acc;
}

// ---------------------------------------------------------------------------
// Kernel 2: projection GEMM  g = x @ Wc + bc,   M=50000, K=1024, N=64
// grid ((M+63)/64, 2), block 256. Tile BM=64, BN=64, BK=32, thread tile 4x4.
// ---------------------------------------------------------------------------
__global__ void proj_kernel(const float* __restrict__ x_gene,
                            const float* __restrict__ x_cell,
                            int N1, int N2) {
    const int half = blockIdx.y;
    const float* x  = half ? x_cell : x_gene;
    const float* Wc = half ? g_Wc2 : g_Wc1;
    const float* bc = half ? g_bc2 : g_bc1;
    float*       g  = half ? g_g2  : g_g1;
    const int M = half ? N2 : N1;

    const int m0 = blockIdx.x * 64;
    if (m0 >= M) return;

    __shared__ float As[32][68];   // A tile transposed: As[k][m]
    __shared__ float Bs[32][68];   // B tile: Bs[k][n]

    const int t  = threadIdx.x;
    const int tx = t & 15;         // n-tile coord
    const int ty = t >> 4;         // m-tile coord

    float acc[4][4] = {};

    const float4* xv = (const float4*)x;     // row stride FDIM/4 = 256
    const float4* Wv = (const float4*)Wc;    // row stride H1DIM/4 = 16

    for (int kk = 0; kk < FDIM / 32; kk++) {
        // Load A tile: 64 rows x 32 cols = 512 float4, 2 per thread
#pragma unroll
        for (int r = 0; r < 2; r++) {
            int i    = t + r * 256;
            int arow = i >> 3;             // 0..63
            int ac4  = i & 7;              // 0..7  (8 float4 = 32 floats)
            int gm   = m0 + arow;
            float4 f4 = make_float4(0.f, 0.f, 0.f, 0.f);
            if (gm < M) f4 = xv[gm * (FDIM / 4) + kk * 8 + ac4];
            As[ac4 * 4 + 0][arow] = f4.x;
            As[ac4 * 4 + 1][arow] = f4.y;
            As[ac4 * 4 + 2][arow] = f4.z;
            As[ac4 * 4 + 3][arow] = f4.w;
        }
        // Load B tile: 32 rows x 64 cols = 512 float4, 2 per thread
#pragma unroll
        for (int r = 0; r < 2; r++) {
            int i    = t + r * 256;
            int brow = i >> 4;             // 0..31
            int bc4  = i & 15;             // 0..15
            float4 f4 = Wv[(kk * 32 + brow) * (H1DIM / 4) + bc4];
            *(float4*)&Bs[brow][bc4 * 4] = f4;
        }
        __syncthreads();

#pragma unroll
        for (int k = 0; k < 32; k++) {
            float4 a = *(const float4*)&As[k][ty * 4];
            float4 b = *(const float4*)&Bs[k][tx * 4];
            acc[0][0] = fmaf(a.x, b.x, acc[0][0]);
            acc[0][1] = fmaf(a.x, b.y, acc[0][1]);
            acc[0][2] = fmaf(a.x, b.z, acc[0][2]);
            acc[0][3] = fmaf(a.x, b.w, acc[0][3]);
            acc[1][0] = fmaf(a.y, b.x, acc[1][0]);
            acc[1][1] = fmaf(a.y, b.y, acc[1][1]);
            acc[1][2] = fmaf(a.y, b.z, acc[1][2]);
            acc[1][3] = fmaf(a.y, b.w, acc[1][3]);
            acc[2][0] = fmaf(a.z, b.x, acc[2][0]);
            acc[2][1] = fmaf(a.z, b.y, acc[2][1]);
            acc[2][2] = fmaf(a.z, b.z, acc[2][2]);
            acc[2][3] = fmaf(a.z, b.w, acc[2][3]);
            acc[3][0] = fmaf(a.w, b.x, acc[3][0]);
            acc[3][1] = fmaf(a.w, b.y, acc[3][1]);
            acc[3][2] = fmaf(a.w, b.z, acc[3][2]);
            acc[3][3] = fmaf(a.w, b.w, acc[3][3]);
        }
        __syncthreads();
    }

    // Epilogue: add bias, store
    float bcr[4];
#pragma unroll
    for (int jj = 0; jj < 4; jj++) bcr[jj] = bc[tx * 4 + jj];
#pragma unroll
    for (int i = 0; i < 4; i++) {
        int gm = m0 + ty * 4 + i;
        if (gm < M) {
#pragma unroll
            for (int jj = 0; jj < 4; jj++)
                g[gm * H1DIM + tx * 4 + jj] = acc[i][jj] + bcr[jj];
        }
    }
}

// ---------------------------------------------------------------------------
// Kernel 3: edge stage.
//   v = relu(g1[s] + g2[d])   (64)
//   u = relu(v @ Wm2 + bm2)   (32)
//   pred = u @ Wm3 + bm3
// Block = 128 threads handles 128 edges. Phase 1: cooperative gather to SMEM.
// Phase 2: lane j owns output column j, Wm2 column j held in registers.
// ---------------------------------------------------------------------------
__global__ void edge_kernel(const int* __restrict__ eidx,
                            const float* __restrict__ Wm2,
                            const float* __restrict__ bm2,
                            const float* __restrict__ Wm3,
                            const float* __restrict__ bm3,
                            float* __restrict__ out,
                            int E, int N1, int N2) {
    __shared__ float vsh[128][68];
    __shared__ int ssh[128], dsh[128];

    const int t  = threadIdx.x;
    const int e0 = blockIdx.x * 128;

    // Load and clamp edge indices
    {
        int e = e0 + t;
        int s = 0, d = 0;
        if (e < E) {
            s = eidx[e];
            d = eidx[E + e];
            s = (s < 0) ? 0 : (s >= N1 ? N1 - 1 : s);
            d = (d < 0) ? 0 : (d >= N2 ? N2 - 1 : d);
        }
        ssh[t] = s;
        dsh[t] = d;
    }
    __syncthreads();

    // Phase 1: gather + add + relu into shared. 16 consecutive threads per edge row.
    const float4* g1v = (const float4*)g_g1;
    const float4* g2v = (const float4*)g_g2;
#pragma unroll
    for (int it = 0; it < 16; it++) {
        int i = t + it * 128;
        int e = i >> 4;
        int c = i & 15;
        if (e0 + e < E) {
            float4 a = g1v[ssh[e] * 16 + c];
            float4 b = g2v[dsh[e] * 16 + c];
            float4 v;
            v.x = fmaxf(a.x + b.x, 0.f);
            v.y = fmaxf(a.y + b.y, 0.f);
            v.z = fmaxf(a.z + b.z, 0.f);
            v.w = fmaxf(a.w + b.w, 0.f);
            *(float4*)&vsh[e][c * 4] = v;
        }
    }
    __syncthreads();

    // Phase 2: lane j (0..31) owns MLP-layer-2 column j.
    const int w = t >> 5;     // warp 0..3
    const int j = t & 31;

    float w2col[64];
#pragma unroll
    for (int k = 0; k < 64; k++) w2col[k] = Wm2[k * H2DIM + j];
    const float w3   = Wm3[j];
    const float bm2j = bm2[j];
    const float bm3v = bm3[0];

    for (int e = w; e < 128; e += 4) {
        int ge = e0 + e;
        if (ge >= E) break;               // uniform within warp
        float a0 = bm2j, a1 = 0.f, a2 = 0.f, a3 = 0.f;
#pragma unroll
        for (int q = 0; q < 16; q++) {
            float4 v = *(const float4*)&vsh[e][q * 4];
            a0 = fmaf(v.x, w2col[4 * q + 0], a0);
            a1 = fmaf(v.y, w2col[4 * q + 1], a1);
            a2 = fmaf(v.z, w2col[4 * q + 2], a2);
            a3 = fmaf(v.w, w2col[4 * q + 3], a3);
        }
        float u = fmaxf((a0 + a1) + (a2 + a3), 0.f);
        float m = u * w3;
#pragma unroll
        for (int off = 16; off; off >>= 1)
            m += __shfl_xor_sync(0xffffffffu, m, off);
        if (j == 0) out[ge] = m + bm3v;
    }
}

// ---------------------------------------------------------------------------
extern "C" void kernel_launch(void* const* d_in, const int* in_sizes, int n_in,
                              void* d_out, int out_size) {
    const float* x_gene = (const float*)d_in[0];
    const float* x_cell = (const float*)d_in[1];
    const int*   eidx   = (const int*)  d_in[2];
    const float* W1     = (const float*)d_in[3];
    const float* b1     = (const float*)d_in[4];
    const float* W2     = (const float*)d_in[5];
    const float* b2     = (const float*)d_in[6];
    const float* Wm1    = (const float*)d_in[7];
    const float* bm1    = (const float*)d_in[8];
    const float* Wm2    = (const float*)d_in[9];
    const float* bm2    = (const float*)d_in[10];
    const float* Wm3    = (const float*)d_in[11];
    const float* bm3    = (const float*)d_in[12];
    float* out = (float*)d_out;

    const int N1 = in_sizes[0] / FDIM;
    const int N2 = in_sizes[1] / FDIM;
    const int E  = in_sizes[2] / 2;

    fold_weights_kernel<<<dim3(FDIM, 2), H1DIM>>>(W1, W2, Wm1);
    fold_bias_kernel<<<1, 128>>>(b1, b2, Wm1, bm1);

    const int Mmax = (N1 > N2) ? N1 : N2;
    proj_kernel<<<dim3((Mmax + 63) / 64, 2), 256>>>(x_gene, x_cell, N1, N2);

    edge_kernel<<<(E + 127) / 128, 128>>>(eidx, Wm2, bm2, Wm3, bm3, out, E, N1, N2);
}

// round 3
// speedup vs baseline: 1.6274x; 1.6274x over previous
#include <cuda_runtime.h>
#include <cuda_bf16.h>
#include <cstdint>

// Problem constants (fixed by dataset: N1=N2=50000, F=1024, D=128, H1=64, H2=32, E=1e6)
#define FDIM  1024
#define DDIM  128
#define H1DIM 64
#define H2DIM 32
#define NMAX  50000

// ---------------------------------------------------------------------------
// Scratch (static device globals — no runtime allocation allowed)
// ---------------------------------------------------------------------------
__device__ __nv_bfloat16 g_WcTh[2 * H1DIM * FDIM];  // folded W, transposed [half][n][k], hi split
__device__ __nv_bfloat16 g_WcTl[2 * H1DIM * FDIM];  // lo split
__device__ float g_bc1[H1DIM];          // b1@Wm1a + bm1
__device__ float g_bc2[H1DIM];          // b2@Wm1b
__device__ float g_g1[NMAX * H1DIM];    // x_gene @ Wc1 + bc1   [50000,64]
__device__ float g_g2[NMAX * H1DIM];    // x_cell @ Wc2 + bc2   [50000,64]

__device__ __forceinline__ uint32_t smem_u32(const void* p) {
    uint32_t a;
    asm("{ .reg .u64 t; cvta.to.shared.u64 t, %1; cvt.u32.u64 %0, t; }" : "=r"(a) : "l"(p));
    return a;
}

#define LDSM_X4(r, a) \
    asm volatile("ldmatrix.sync.aligned.m8n8.x4.shared.b16 {%0,%1,%2,%3}, [%4];" \
                 : "=r"((r)[0]), "=r"((r)[1]), "=r"((r)[2]), "=r"((r)[3]) : "r"(a))

#define MMA_BF16(c, a, b0, b1) \
    asm volatile("mma.sync.aligned.m16n8k16.row.col.f32.bf16.bf16.f32 " \
                 "{%0,%1,%2,%3}, {%4,%5,%6,%7}, {%8,%9}, {%0,%1,%2,%3};" \
                 : "+f"((c)[0]), "+f"((c)[1]), "+f"((c)[2]), "+f"((c)[3]) \
                 : "r"((a)[0]), "r"((a)[1]), "r"((a)[2]), "r"((a)[3]), "r"(b0), "r"(b1))

// ---------------------------------------------------------------------------
// Kernel 1: fold W{1,2} (1024x128) @ Wm1 halves (128x64) -> transposed bf16 hi/lo
// grid (1024, 2), block 64
// ---------------------------------------------------------------------------
__global__ void fold_weights_kernel(const float* __restrict__ W1,
                                    const float* __restrict__ W2,
                                    const float* __restrict__ Wm1) {
    const int f    = blockIdx.x;       // k index
    const int half = blockIdx.y;
    const int j    = threadIdx.x;      // n index 0..63
    const float* W = half ? W2 : W1;
    const int off = half * DDIM;
    float acc = 0.f;
#pragma unroll 8
    for (int d = 0; d < DDIM; d++)
        acc = fmaf(W[f * DDIM + d], Wm1[(off + d) * H1DIM + j], acc);
    __nv_bfloat16 hi = __float2bfloat16(acc);
    __nv_bfloat16 lo = __float2bfloat16(acc - __bfloat162float(hi));
    const int idx = (half * H1DIM + j) * FDIM + f;
    g_WcTh[idx] = hi;
    g_WcTl[idx] = lo;
}

__global__ void fold_bias_kernel(const float* __restrict__ b1,
                                 const float* __restrict__ b2,
                                 const float* __restrict__ Wm1,
                                 const float* __restrict__ bm1) {
    const int t = threadIdx.x;
    if (t >= 128) return;
    const int j = t & 63;
    const int half = t >> 6;
    const float* b = half ? b2 : b1;
    const int off = half * DDIM;
    float acc = half ? 0.f : bm1[j];
#pragma unroll 8
    for (int d = 0; d < DDIM; d++)
        acc = fmaf(b[d], Wm1[(off + d) * H1DIM + j], acc);
    (half ? g_bc2 : g_bc1)[j] = acc;
}

// ---------------------------------------------------------------------------
// Kernel 2: mma.sync bf16-split projection GEMM  g = x @ Wc + bc
// M=50000, K=1024, N=64. BM=128, BN=64, BK=32, 256 threads (8 warps, 4x2).
// D = Ah*Bh + Ah*Bl + Al*Bh (fp32 acc); lo*lo dropped (~2^-18).
// ---------------------------------------------------------------------------
#define A_STRIDE 80   // 32 bf16 = 64B row, padded to 80B (conflict-free LDSM)
#define B_STRIDE 80

__global__ void __launch_bounds__(256)
proj_mma_kernel(const float* __restrict__ x_gene,
                const float* __restrict__ x_cell,
                int N1, int N2) {
    __shared__ __align__(16) char as_hi[128 * A_STRIDE];
    __shared__ __align__(16) char as_lo[128 * A_STRIDE];
    __shared__ __align__(16) char bs_hi[64 * B_STRIDE];
    __shared__ __align__(16) char bs_lo[64 * B_STRIDE];

    const int t   = threadIdx.x;
    const int wid = t >> 5;
    const int l   = t & 31;
    const int half = blockIdx.y;

    const float* x = half ? x_cell : x_gene;
    const char* WTh = (const char*)(g_WcTh + half * H1DIM * FDIM);
    const char* WTl = (const char*)(g_WcTl + half * H1DIM * FDIM);
    const float* bc = half ? g_bc2 : g_bc1;
    float* g = half ? g_g2 : g_g1;
    const int M  = half ? N2 : N1;
    const int m0 = blockIdx.x * 128;
    if (m0 >= M) return;

    const uint32_t asb_hi = smem_u32(as_hi);
    const uint32_t asb_lo = smem_u32(as_lo);
    const uint32_t bsb_hi = smem_u32(bs_hi);
    const uint32_t bsb_lo = smem_u32(bs_lo);

    const int m0w = (wid & 3) * 32;    // warp m offset within tile
    const int n0w = (wid >> 2) * 32;   // warp n offset

    float acc[2][4][4] = {};

    const float4* xv = (const float4*)x;
    const int arow = t >> 3;           // 0..31
    const int ac4  = t & 7;            // float4 col within BK=32 (8 float4)
    const int brow = t >> 2;           // 0..63
    const int bq   = t & 3;            // 16B chunk within 64B row

    // Precompute clamped global rows for the 4 A sub-rows this thread loads
    size_t gmr[4];
#pragma unroll
    for (int r = 0; r < 4; r++) {
        int row = arow + 32 * r;
        int gm = m0 + row;
        gmr[r] = (size_t)((gm < M) ? gm : (M - 1));
    }

    // LDSM source addresses (constant across K loop)
    uint32_t a_addr_hi[2], a_addr_lo[2], b_addr_hi[2], b_addr_lo[2];
#pragma unroll
    for (int mt = 0; mt < 2; mt++) {
        uint32_t off = (uint32_t)((m0w + mt * 16 + (l & 15)) * A_STRIDE + (l >> 4) * 16);
        a_addr_hi[mt] = asb_hi + off;
        a_addr_lo[mt] = asb_lo + off;
    }
#pragma unroll
    for (int gpair = 0; gpair < 2; gpair++) {
        uint32_t off = (uint32_t)((n0w + gpair * 16 + ((l >> 4) * 8) + (l & 7)) * B_STRIDE
                                  + ((l >> 3) & 1) * 16);
        b_addr_hi[gpair] = bsb_hi + off;
        b_addr_lo[gpair] = bsb_lo + off;
    }

    for (int kk = 0; kk < FDIM / 32; kk++) {
        // ---- A tile: 128 x 32 fp32 -> bf16 hi/lo ----
#pragma unroll
        for (int r = 0; r < 4; r++) {
            const int row = arow + 32 * r;
            float4 v = xv[gmr[r] * (FDIM / 4) + kk * 8 + ac4];
            __nv_bfloat16 hx = __float2bfloat16(v.x);
            __nv_bfloat16 hy = __float2bfloat16(v.y);
            __nv_bfloat16 hz = __float2bfloat16(v.z);
            __nv_bfloat16 hw = __float2bfloat16(v.w);
            __nv_bfloat162 h01 = __halves2bfloat162(hx, hy);
            __nv_bfloat162 h23 = __halves2bfloat162(hz, hw);
            __nv_bfloat162 l01 = __floats2bfloat162_rn(v.x - __bfloat162float(hx),
                                                       v.y - __bfloat162float(hy));
            __nv_bfloat162 l23 = __floats2bfloat162_rn(v.z - __bfloat162float(hz),
                                                       v.w - __bfloat162float(hw));
            const uint32_t off = (uint32_t)(row * A_STRIDE + ac4 * 8);
            uint2 uh; uh.x = *(uint32_t*)&h01; uh.y = *(uint32_t*)&h23;
            uint2 ul; ul.x = *(uint32_t*)&l01; ul.y = *(uint32_t*)&l23;
            *(uint2*)(as_hi + off) = uh;
            *(uint2*)(as_lo + off) = ul;
        }
        // ---- B tile: 64 rows(n) x 32 bf16(k) per split (already split in gmem) ----
        {
            const size_t goff = (size_t)brow * (FDIM * 2) + kk * 64 + bq * 16;
            const uint32_t soff = (uint32_t)(brow * B_STRIDE + bq * 16);
            *(uint4*)(bs_hi + soff) = *(const uint4*)(WTh + goff);
            *(uint4*)(bs_lo + soff) = *(const uint4*)(WTl + goff);
        }
        __syncthreads();

        // ---- MMA phase ----
#pragma unroll
        for (int kc = 0; kc < 2; kc++) {
            const uint32_t ko = kc * 32;
            uint32_t ah[2][4], al[2][4], bh[2][4], bl[2][4];
#pragma unroll
            for (int mt = 0; mt < 2; mt++) {
                LDSM_X4(ah[mt], a_addr_hi[mt] + ko);
                LDSM_X4(al[mt], a_addr_lo[mt] + ko);
            }
#pragma unroll
            for (int gp = 0; gp < 2; gp++) {
                LDSM_X4(bh[gp], b_addr_hi[gp] + ko);
                LDSM_X4(bl[gp], b_addr_lo[gp] + ko);
            }
#pragma unroll
            for (int mt = 0; mt < 2; mt++) {
#pragma unroll
                for (int nt = 0; nt < 4; nt++) {
                    const int gp = nt >> 1;
                    const int br = (nt & 1) * 2;
                    MMA_BF16(acc[mt][nt], ah[mt], bh[gp][br], bh[gp][br + 1]);
                    MMA_BF16(acc[mt][nt], ah[mt], bl[gp][br], bl[gp][br + 1]);
                    MMA_BF16(acc[mt][nt], al[mt], bh[gp][br], bh[gp][br + 1]);
                }
            }
        }
        __syncthreads();
    }

    // ---- Epilogue: c-frag -> g (+bias) ----
#pragma unroll
    for (int mt = 0; mt < 2; mt++) {
#pragma unroll
        for (int nt = 0; nt < 4; nt++) {
            const int col = n0w + nt * 8 + 2 * (l & 3);
            const float bx = bc[col], by = bc[col + 1];
            const int r0 = m0 + m0w + mt * 16 + (l >> 2);
            if (r0 < M) {
                float2 o; o.x = acc[mt][nt][0] + bx; o.y = acc[mt][nt][1] + by;
                *(float2*)&g[(size_t)r0 * H1DIM + col] = o;
            }
            const int r1 = r0 + 8;
            if (r1 < M) {
                float2 o; o.x = acc[mt][nt][2] + bx; o.y = acc[mt][nt][3] + by;
                *(float2*)&g[(size_t)r1 * H1DIM + col] = o;
            }
        }
    }
}

// ---------------------------------------------------------------------------
// Kernel 3: edge stage with packed f32x2 FMA in the MLP-2 layer.
//   v = relu(g1[s] + g2[d]) (64); u = relu(v @ Wm2 + bm2) (32); out = u @ Wm3 + bm3
// ---------------------------------------------------------------------------
__global__ void edge_kernel(const int* __restrict__ eidx,
                            const float* __restrict__ Wm2,
                            const float* __restrict__ bm2,
                            const float* __restrict__ Wm3,
                            const float* __restrict__ bm3,
                            float* __restrict__ out,
                            int E, int N1, int N2) {
    __shared__ __align__(16) float vsh[128][68];
    __shared__ int ssh[128], dsh[128];

    const int t  = threadIdx.x;
    const int e0 = blockIdx.x * 128;

    {
        int e = e0 + t;
        int s = 0, d = 0;
        if (e < E) {
            s = eidx[e];
            d = eidx[E + e];
            s = (s < 0) ? 0 : (s >= N1 ? N1 - 1 : s);
            d = (d < 0) ? 0 : (d >= N2 ? N2 - 1 : d);
        }
        ssh[t] = s;
        dsh[t] = d;
    }
    __syncthreads();

    const float4* g1v = (const float4*)g_g1;
    const float4* g2v = (const float4*)g_g2;
#pragma unroll
    for (int it = 0; it < 16; it++) {
        int i = t + it * 128;
        int e = i >> 4;
        int c = i & 15;
        if (e0 + e < E) {
            float4 a = g1v[ssh[e] * 16 + c];
            float4 b = g2v[dsh[e] * 16 + c];
            float4 v;
            v.x = fmaxf(a.x + b.x, 0.f);
            v.y = fmaxf(a.y + b.y, 0.f);
            v.z = fmaxf(a.z + b.z, 0.f);
            v.w = fmaxf(a.w + b.w, 0.f);
            *(float4*)&vsh[e][c * 4] = v;
        }
    }
    __syncthreads();

    const int w = t >> 5;
    const int j = t & 31;

    // Pack Wm2 column j as 32 f32x2 pairs: wp[p] = {Wm2[2p][j], Wm2[2p+1][j]}
    unsigned long long wp[32];
#pragma unroll
    for (int p = 0; p < 32; p++) {
        float w0 = Wm2[(2 * p) * H2DIM + j];
        float w1 = Wm2[(2 * p + 1) * H2DIM + j];
        asm("mov.b64 %0, {%1, %2};" : "=l"(wp[p]) : "f"(w0), "f"(w1));
    }
    const float w3   = Wm3[j];
    const float bm2j = bm2[j];
    const float bm3v = bm3[0];

    for (int e = w; e < 128; e += 4) {
        int ge = e0 + e;
        if (ge >= E) break;               // uniform within warp
        unsigned long long a01, a23 = 0ull;   // {0.f,0.f}
        asm("mov.b64 %0, {%1, %2};" : "=l"(a01) : "f"(bm2j), "f"(0.f));
        const uint32_t vaddr = smem_u32(&vsh[e][0]);
#pragma unroll
        for (int q = 0; q < 16; q++) {
            unsigned long long p01, p23;
            asm("ld.shared.v2.u64 {%0, %1}, [%2];"
                : "=l"(p01), "=l"(p23) : "r"(vaddr + q * 16));
            asm("fma.rn.f32x2 %0, %1, %2, %0;" : "+l"(a01) : "l"(p01), "l"(wp[2 * q]));
            asm("fma.rn.f32x2 %0, %1, %2, %0;" : "+l"(a23) : "l"(p23), "l"(wp[2 * q + 1]));
        }
        float s0, s1, s2, s3;
        asm("mov.b64 {%0, %1}, %2;" : "=f"(s0), "=f"(s1) : "l"(a01));
        asm("mov.b64 {%0, %1}, %2;" : "=f"(s2), "=f"(s3) : "l"(a23));
        float u = fmaxf((s0 + s1) + (s2 + s3), 0.f);
        float m = u * w3;
#pragma unroll
        for (int off = 16; off; off >>= 1)
            m += __shfl_xor_sync(0xffffffffu, m, off);
        if (j == 0) out[ge] = m + bm3v;
    }
}

// ---------------------------------------------------------------------------
extern "C" void kernel_launch(void* const* d_in, const int* in_sizes, int n_in,
                              void* d_out, int out_size) {
    const float* x_gene = (const float*)d_in[0];
    const float* x_cell = (const float*)d_in[1];
    const int*   eidx   = (const int*)  d_in[2];
    const float* W1     = (const float*)d_in[3];
    const float* b1     = (const float*)d_in[4];
    const float* W2     = (const float*)d_in[5];
    const float* b2     = (const float*)d_in[6];
    const float* Wm1    = (const float*)d_in[7];
    const float* bm1    = (const float*)d_in[8];
    const float* Wm2    = (const float*)d_in[9];
    const float* bm2    = (const float*)d_in[10];
    const float* Wm3    = (const float*)d_in[11];
    const float* bm3    = (const float*)d_in[12];
    float* out = (float*)d_out;

    const int N1 = in_sizes[0] / FDIM;
    const int N2 = in_sizes[1] / FDIM;
    const int E  = in_sizes[2] / 2;

    fold_weights_kernel<<<dim3(FDIM, 2), H1DIM>>>(W1, W2, Wm1);
    fold_bias_kernel<<<1, 128>>>(b1, b2, Wm1, bm1);

    const int Mmax = (N1 > N2) ? N1 : N2;
    proj_mma_kernel<<<dim3((Mmax + 127) / 128, 2), 256>>>(x_gene, x_cell, N1, N2);

    edge_kernel<<<(E + 127) / 128, 128>>>(eidx, Wm2, bm2, Wm3, bm3, out, E, N1, N2);
}

// round 4
// speedup vs baseline: 2.2790x; 1.4003x over previous
#include <cuda_runtime.h>
#include <cuda_bf16.h>
#include <cstdint>

// Problem constants (fixed by dataset: N1=N2=50000, F=1024, D=128, H1=64, H2=32, E=1e6)
#define FDIM  1024
#define DDIM  128
#define H1DIM 64
#define H2DIM 32
#define NMAX  50000

// ---------------------------------------------------------------------------
// Scratch (static device globals — no runtime allocation allowed)
// ---------------------------------------------------------------------------
__device__ __nv_bfloat16 g_WcTh[2 * H1DIM * FDIM];  // folded W, transposed [half][n][k], hi split
__device__ __nv_bfloat16 g_WcTl[2 * H1DIM * FDIM];  // lo split
__device__ __nv_bfloat16 g_Wm2Th[H2DIM * H1DIM];    // Wm2 transposed [n=32][k=64], hi
__device__ __nv_bfloat16 g_Wm2Tl[H2DIM * H1DIM];    // lo
__device__ float g_bc1[H1DIM];
__device__ float g_bc2[H1DIM];
__device__ float g_g1[NMAX * H1DIM];    // x_gene @ Wc1 + bc1   [50000,64]
__device__ float g_g2[NMAX * H1DIM];    // x_cell @ Wc2 + bc2   [50000,64]

__device__ __forceinline__ uint32_t smem_u32(const void* p) {
    uint32_t a;
    asm("{ .reg .u64 t; cvta.to.shared.u64 t, %1; cvt.u32.u64 %0, t; }" : "=r"(a) : "l"(p));
    return a;
}

#define LDSM_X4(r, a) \
    asm volatile("ldmatrix.sync.aligned.m8n8.x4.shared.b16 {%0,%1,%2,%3}, [%4];" \
                 : "=r"((r)[0]), "=r"((r)[1]), "=r"((r)[2]), "=r"((r)[3]) : "r"(a))

#define MMA_BF16(c, a, b0, b1) \
    asm volatile("mma.sync.aligned.m16n8k16.row.col.f32.bf16.bf16.f32 " \
                 "{%0,%1,%2,%3}, {%4,%5,%6,%7}, {%8,%9}, {%0,%1,%2,%3};" \
                 : "+f"((c)[0]), "+f"((c)[1]), "+f"((c)[2]), "+f"((c)[3]) \
                 : "r"((a)[0]), "r"((a)[1]), "r"((a)[2]), "r"((a)[3]), "r"(b0), "r"(b1))

#define CP_ASYNC16(dst, src) \
    asm volatile("cp.async.ca.shared.global [%0], [%1], 16;" :: "r"(dst), "l"(src))
#define CP_COMMIT() asm volatile("cp.async.commit_group;" ::: "memory")
#define CP_WAIT1()  asm volatile("cp.async.wait_group 1;" ::: "memory")

__device__ __forceinline__ void split_bf16x2(float a, float b, uint32_t& hi, uint32_t& lo) {
    __nv_bfloat16 ha = __float2bfloat16(a);
    __nv_bfloat16 hb = __float2bfloat16(b);
    __nv_bfloat162 h = __halves2bfloat162(ha, hb);
    __nv_bfloat162 l = __floats2bfloat162_rn(a - __bfloat162float(ha),
                                             b - __bfloat162float(hb));
    hi = *(uint32_t*)&h;
    lo = *(uint32_t*)&l;
}

// ---------------------------------------------------------------------------
// Kernel 1: fold W{1,2} @ Wm1 halves -> transposed bf16 hi/lo. grid (1024,2) x 64
// ---------------------------------------------------------------------------
__global__ void fold_weights_kernel(const float* __restrict__ W1,
                                    const float* __restrict__ W2,
                                    const float* __restrict__ Wm1) {
    const int f    = blockIdx.x;
    const int half = blockIdx.y;
    const int j    = threadIdx.x;
    const float* W = half ? W2 : W1;
    const int off = half * DDIM;
    float acc = 0.f;
#pragma unroll 8
    for (int d = 0; d < DDIM; d++)
        acc = fmaf(W[f * DDIM + d], Wm1[(off + d) * H1DIM + j], acc);
    __nv_bfloat16 hi = __float2bfloat16(acc);
    __nv_bfloat16 lo = __float2bfloat16(acc - __bfloat162float(hi));
    const int idx = (half * H1DIM + j) * FDIM + f;
    g_WcTh[idx] = hi;
    g_WcTl[idx] = lo;
}

__global__ void fold_bias_kernel(const float* __restrict__ b1,
                                 const float* __restrict__ b2,
                                 const float* __restrict__ Wm1,
                                 const float* __restrict__ bm1) {
    const int t = threadIdx.x;
    if (t >= 128) return;
    const int j = t & 63;
    const int half = t >> 6;
    const float* b = half ? b2 : b1;
    const int off = half * DDIM;
    float acc = half ? 0.f : bm1[j];
#pragma unroll 8
    for (int d = 0; d < DDIM; d++)
        acc = fmaf(b[d], Wm1[(off + d) * H1DIM + j], acc);
    (half ? g_bc2 : g_bc1)[j] = acc;
}

// Kernel 1c: transpose+split Wm2 [64,32] -> [32][64] bf16 hi/lo. 1 block x 256
__global__ void fold_wm2_kernel(const float* __restrict__ Wm2) {
    for (int idx = threadIdx.x; idx < H2DIM * H1DIM; idx += 256) {
        const int n = idx & (H2DIM - 1);
        const int k = idx >> 5;
        float v = Wm2[k * H2DIM + n];
        __nv_bfloat16 hi = __float2bfloat16(v);
        __nv_bfloat16 lo = __float2bfloat16(v - __bfloat162float(hi));
        g_Wm2Th[n * H1DIM + k] = hi;
        g_Wm2Tl[n * H1DIM + k] = lo;
    }
}

// ---------------------------------------------------------------------------
// Kernel 2: mma.sync bf16-split projection GEMM  g = x @ Wc + bc
// BM=128, BN=64, BK=32, 256 threads. A reg-prefetched, B cp.async double-buffered.
// ---------------------------------------------------------------------------
#define A_STRIDE 80
#define B_STRIDE 80
#define B_BUF    (H1DIM * B_STRIDE)   // 5120

__global__ void __launch_bounds__(256)
proj_mma_kernel(const float* __restrict__ x_gene,
                const float* __restrict__ x_cell,
                int N1, int N2) {
    __shared__ __align__(16) char as_hi[128 * A_STRIDE];
    __shared__ __align__(16) char as_lo[128 * A_STRIDE];
    __shared__ __align__(16) char bs_hi[2 * B_BUF];
    __shared__ __align__(16) char bs_lo[2 * B_BUF];

    const int t   = threadIdx.x;
    const int wid = t >> 5;
    const int l   = t & 31;
    const int half = blockIdx.y;

    const float* x = half ? x_cell : x_gene;
    const char* WTh = (const char*)(g_WcTh + half * H1DIM * FDIM);
    const char* WTl = (const char*)(g_WcTl + half * H1DIM * FDIM);
    const float* bc = half ? g_bc2 : g_bc1;
    float* g = half ? g_g2 : g_g1;
    const int M  = half ? N2 : N1;
    const int m0 = blockIdx.x * 128;
    if (m0 >= M) return;

    const uint32_t asb_hi = smem_u32(as_hi);
    const uint32_t asb_lo = smem_u32(as_lo);
    const uint32_t bsb_hi = smem_u32(bs_hi);
    const uint32_t bsb_lo = smem_u32(bs_lo);

    const int m0w = (wid & 3) * 32;
    const int n0w = (wid >> 2) * 32;

    float acc[2][4][4] = {};

    const float4* xv = (const float4*)x;
    const int arow = t >> 3;           // 0..31
    const int ac4  = t & 7;
    const int brow = t >> 2;           // 0..63
    const int bq   = t & 3;

    size_t gmr[4];
#pragma unroll
    for (int r = 0; r < 4; r++) {
        int gm = m0 + arow + 32 * r;
        gmr[r] = (size_t)((gm < M) ? gm : (M - 1));
    }

    uint32_t a_addr_hi[2], a_addr_lo[2], b_off[2];
#pragma unroll
    for (int mt = 0; mt < 2; mt++) {
        uint32_t off = (uint32_t)((m0w + mt * 16 + (l & 15)) * A_STRIDE + (l >> 4) * 16);
        a_addr_hi[mt] = asb_hi + off;
        a_addr_lo[mt] = asb_lo + off;
    }
#pragma unroll
    for (int gp = 0; gp < 2; gp++)
        b_off[gp] = (uint32_t)((n0w + gp * 16 + ((l >> 4) * 8) + (l & 7)) * B_STRIDE
                               + ((l >> 3) & 1) * 16);

    const size_t bgo = (size_t)brow * (FDIM * 2) + bq * 16;
    const uint32_t bso = (uint32_t)(brow * B_STRIDE + bq * 16);

    // Prologue: A chunk 0 -> regs, B chunk 0 -> buf 0
    float4 va[4];
#pragma unroll
    for (int r = 0; r < 4; r++) va[r] = xv[gmr[r] * (FDIM / 4) + ac4];
    CP_ASYNC16(bsb_hi + bso, WTh + bgo);
    CP_ASYNC16(bsb_lo + bso, WTl + bgo);
    CP_COMMIT();

    for (int kk = 0; kk < FDIM / 32; kk++) {
        const int buf = kk & 1;
        // ---- convert + STS current A ----
#pragma unroll
        for (int r = 0; r < 4; r++) {
            uint2 uh, ul;
            split_bf16x2(va[r].x, va[r].y, uh.x, ul.x);
            split_bf16x2(va[r].z, va[r].w, uh.y, ul.y);
            const uint32_t off = (uint32_t)((arow + 32 * r) * A_STRIDE + ac4 * 8);
            *(uint2*)(as_hi + off) = uh;
            *(uint2*)(as_lo + off) = ul;
        }
        // ---- prefetch next B via cp.async ----
        if (kk < FDIM / 32 - 1) {
            const uint32_t nso = (buf ^ 1) * B_BUF + bso;
            CP_ASYNC16(bsb_hi + nso, WTh + bgo + (size_t)(kk + 1) * 64);
            CP_ASYNC16(bsb_lo + nso, WTl + bgo + (size_t)(kk + 1) * 64);
        }
        CP_COMMIT();
        CP_WAIT1();                    // current B landed
        __syncthreads();
        // ---- prefetch next A into regs (overlaps MMA) ----
        if (kk < FDIM / 32 - 1) {
#pragma unroll
            for (int r = 0; r < 4; r++)
                va[r] = xv[gmr[r] * (FDIM / 4) + (kk + 1) * 8 + ac4];
        }
        // ---- MMA phase ----
        const uint32_t bbase = buf * B_BUF;
#pragma unroll
        for (int kc = 0; kc < 2; kc++) {
            const uint32_t ko = kc * 32;
            uint32_t ah[2][4], al[2][4], bh[2][4], bl[2][4];
#pragma unroll
            for (int mt = 0; mt < 2; mt++) {
                LDSM_X4(ah[mt], a_addr_hi[mt] + ko);
                LDSM_X4(al[mt], a_addr_lo[mt] + ko);
            }
#pragma unroll
            for (int gp = 0; gp < 2; gp++) {
                LDSM_X4(bh[gp], bsb_hi + bbase + b_off[gp] + ko);
                LDSM_X4(bl[gp], bsb_lo + bbase + b_off[gp] + ko);
            }
#pragma unroll
            for (int mt = 0; mt < 2; mt++) {
#pragma unroll
                for (int nt = 0; nt < 4; nt++) {
                    const int gp = nt >> 1;
                    const int br = (nt & 1) * 2;
                    MMA_BF16(acc[mt][nt], ah[mt], bh[gp][br], bh[gp][br + 1]);
                    MMA_BF16(acc[mt][nt], ah[mt], bl[gp][br], bl[gp][br + 1]);
                    MMA_BF16(acc[mt][nt], al[mt], bh[gp][br], bh[gp][br + 1]);
                }
            }
        }
        __syncthreads();
    }

    // ---- Epilogue ----
#pragma unroll
    for (int mt = 0; mt < 2; mt++) {
#pragma unroll
        for (int nt = 0; nt < 4; nt++) {
            const int col = n0w + nt * 8 + 2 * (l & 3);
            const float bx = bc[col], by = bc[col + 1];
            const int r0 = m0 + m0w + mt * 16 + (l >> 2);
            if (r0 < M) {
                float2 o; o.x = acc[mt][nt][0] + bx; o.y = acc[mt][nt][1] + by;
                *(float2*)&g[(size_t)r0 * H1DIM + col] = o;
            }
            const int r1 = r0 + 8;
            if (r1 < M) {
                float2 o; o.x = acc[mt][nt][2] + bx; o.y = acc[mt][nt][3] + by;
                *(float2*)&g[(size_t)r1 * H1DIM + col] = o;
            }
        }
    }
}

// ---------------------------------------------------------------------------
// Kernel 3: edge stage, layer 2 via mma.sync.
//   v = relu(g1[s]+g2[d]) -> bf16 hi/lo smem; u = relu(v@Wm2+bm2); out = u@Wm3+bm3
// Block 128 threads / 128 edges. Each warp: M=32 edges, N=32, K=64.
// ---------------------------------------------------------------------------
#define EV_STRIDE 144   // 64 bf16 = 128B + 16B pad (conflict-free ldmatrix)

__global__ void __launch_bounds__(128)
edge_kernel(const int* __restrict__ eidx,
            const float* __restrict__ bm2,
            const float* __restrict__ Wm3,
            const float* __restrict__ bm3,
            float* __restrict__ out,
            int E, int N1, int N2) {
    __shared__ __align__(16) char vhi[128 * EV_STRIDE];
    __shared__ __align__(16) char vlo[128 * EV_STRIDE];
    __shared__ __align__(16) char wh[H2DIM * EV_STRIDE];
    __shared__ __align__(16) char wl[H2DIM * EV_STRIDE];
    __shared__ int ssh[128], dsh[128];

    const int t  = threadIdx.x;
    const int w  = t >> 5;
    const int l  = t & 31;
    const int e0 = blockIdx.x * 128;

    // Edge indices (clamped; OOB edges read row 0, stores guarded)
    {
        int e = e0 + t;
        int s = 0, d = 0;
        if (e < E) {
            s = eidx[e];
            d = eidx[E + e];
            s = (s < 0) ? 0 : (s >= N1 ? N1 - 1 : s);
            d = (d < 0) ? 0 : (d >= N2 ? N2 - 1 : d);
        }
        ssh[t] = s;
        dsh[t] = d;
    }
    // Wm2T tiles into smem: 32 rows x 128B per split, 2x16B per thread
    {
        const int row = t >> 2;
        const int q   = t & 3;
        const size_t go = (size_t)row * (H1DIM * 2) + q * 32;
        const uint32_t so = (uint32_t)(row * EV_STRIDE + q * 32);
        *(uint4*)(wh + so)      = *(const uint4*)((const char*)g_Wm2Th + go);
        *(uint4*)(wh + so + 16) = *(const uint4*)((const char*)g_Wm2Th + go + 16);
        *(uint4*)(wl + so)      = *(const uint4*)((const char*)g_Wm2Tl + go);
        *(uint4*)(wl + so + 16) = *(const uint4*)((const char*)g_Wm2Tl + go + 16);
    }
    __syncthreads();

    // Phase 1: gather + add + relu -> bf16 hi/lo v tiles
    const float4* g1v = (const float4*)g_g1;
    const float4* g2v = (const float4*)g_g2;
#pragma unroll
    for (int it = 0; it < 16; it++) {
        const int i = t + it * 128;
        const int e = i >> 4;
        const int c = i & 15;
        float4 a = g1v[(size_t)ssh[e] * 16 + c];
        float4 b = g2v[(size_t)dsh[e] * 16 + c];
        float v0 = fmaxf(a.x + b.x, 0.f);
        float v1 = fmaxf(a.y + b.y, 0.f);
        float v2 = fmaxf(a.z + b.z, 0.f);
        float v3 = fmaxf(a.w + b.w, 0.f);
        uint2 uh, ul;
        split_bf16x2(v0, v1, uh.x, ul.x);
        split_bf16x2(v2, v3, uh.y, ul.y);
        const uint32_t off = (uint32_t)(e * EV_STRIDE + c * 8);
        *(uint2*)(vhi + off) = uh;
        *(uint2*)(vlo + off) = ul;
    }
    __syncthreads();

    // Phase 2: per-warp v[32,64] @ Wm2T[32,64]^T via mma.sync (hi/lo 3-product)
    const uint32_t vb_hi = smem_u32(vhi);
    const uint32_t vb_lo = smem_u32(vlo);
    const uint32_t wb_hi = smem_u32(wh);
    const uint32_t wb_lo = smem_u32(wl);

    uint32_t a_hi[2], a_lo[2], b_hi[2], b_lo[2];
#pragma unroll
    for (int mt = 0; mt < 2; mt++) {
        const uint32_t off = (uint32_t)((w * 32 + mt * 16 + (l & 15)) * EV_STRIDE + (l >> 4) * 16);
        a_hi[mt] = vb_hi + off;
        a_lo[mt] = vb_lo + off;
    }
#pragma unroll
    for (int gp = 0; gp < 2; gp++) {
        const uint32_t off = (uint32_t)((gp * 16 + ((l >> 4) * 8) + (l & 7)) * EV_STRIDE
                                        + ((l >> 3) & 1) * 16);
        b_hi[gp] = wb_hi + off;
        b_lo[gp] = wb_lo + off;
    }

    float acc[2][4][4] = {};
#pragma unroll
    for (int ks = 0; ks < 4; ks++) {
        const uint32_t ko = ks * 32;
        uint32_t ah[2][4], al[2][4], bh[2][4], bl[2][4];
#pragma unroll
        for (int mt = 0; mt < 2; mt++) {
            LDSM_X4(ah[mt], a_hi[mt] + ko);
            LDSM_X4(al[mt], a_lo[mt] + ko);
        }
#pragma unroll
        for (int gp = 0; gp < 2; gp++) {
            LDSM_X4(bh[gp], b_hi[gp] + ko);
            LDSM_X4(bl[gp], b_lo[gp] + ko);
        }
#pragma unroll
        for (int mt = 0; mt < 2; mt++) {
#pragma unroll
            for (int nt = 0; nt < 4; nt++) {
                const int gp = nt >> 1;
                const int br = (nt & 1) * 2;
                MMA_BF16(acc[mt][nt], ah[mt], bh[gp][br], bh[gp][br + 1]);
                MMA_BF16(acc[mt][nt], ah[mt], bl[gp][br], bl[gp][br + 1]);
                MMA_BF16(acc[mt][nt], al[mt], bh[gp][br], bh[gp][br + 1]);
            }
        }
    }

    // Epilogue: u = relu(acc + bm2), partial = u * Wm3, reduce over N=32
    float bm2v[4][2], wm3v[4][2];
#pragma unroll
    for (int nt = 0; nt < 4; nt++) {
        const int col = nt * 8 + 2 * (l & 3);
        bm2v[nt][0] = bm2[col];     bm2v[nt][1] = bm2[col + 1];
        wm3v[nt][0] = Wm3[col];     wm3v[nt][1] = Wm3[col + 1];
    }
    const float bm3v = bm3[0];

#pragma unroll
    for (int mt = 0; mt < 2; mt++) {
#pragma unroll
        for (int r = 0; r < 2; r++) {
            float s = 0.f;
#pragma unroll
            for (int nt = 0; nt < 4; nt++) {
                float c0 = fmaxf(acc[mt][nt][2 * r + 0] + bm2v[nt][0], 0.f);
                float c1 = fmaxf(acc[mt][nt][2 * r + 1] + bm2v[nt][1], 0.f);
                s = fmaf(c0, wm3v[nt][0], s);
                s = fmaf(c1, wm3v[nt][1], s);
            }
            s += __shfl_xor_sync(0xffffffffu, s, 1);
            s += __shfl_xor_sync(0xffffffffu, s, 2);
            if ((l & 3) == 0) {
                const int ge = e0 + w * 32 + mt * 16 + r * 8 + (l >> 2);
                if (ge < E) out[ge] = s + bm3v;
            }
        }
    }
}

// ---------------------------------------------------------------------------
extern "C" void kernel_launch(void* const* d_in, const int* in_sizes, int n_in,
                              void* d_out, int out_size) {
    const float* x_gene = (const float*)d_in[0];
    const float* x_cell = (const float*)d_in[1];
    const int*   eidx   = (const int*)  d_in[2];
    const float* W1     = (const float*)d_in[3];
    const float* b1     = (const float*)d_in[4];
    const float* W2     = (const float*)d_in[5];
    const float* b2     = (const float*)d_in[6];
    const float* Wm1    = (const float*)d_in[7];
    const float* bm1    = (const float*)d_in[8];
    const float* Wm2    = (const float*)d_in[9];
    const float* bm2    = (const float*)d_in[10];
    const float* Wm3    = (const float*)d_in[11];
    const float* bm3    = (const float*)d_in[12];
    float* out = (float*)d_out;

    const int N1 = in_sizes[0] / FDIM;
    const int N2 = in_sizes[1] / FDIM;
    const int E  = in_sizes[2] / 2;

    fold_weights_kernel<<<dim3(FDIM, 2), H1DIM>>>(W1, W2, Wm1);
    fold_bias_kernel<<<1, 128>>>(b1, b2, Wm1, bm1);
    fold_wm2_kernel<<<1, 256>>>(Wm2);

    const int Mmax = (N1 > N2) ? N1 : N2;
    proj_mma_kernel<<<dim3((Mmax + 127) / 128, 2), 256>>>(x_gene, x_cell, N1, N2);

    edge_kernel<<<(E + 127) / 128, 128>>>(eidx, bm2, Wm3, bm3, out, E, N1, N2);
}

// round 5
// speedup vs baseline: 2.3785x; 1.0437x over previous
#include <cuda_runtime.h>
#include <cuda_bf16.h>
#include <cstdint>

// Problem constants (fixed by dataset: N1=N2=50000, F=1024, D=128, H1=64, H2=32, E=1e6)
#define FDIM  1024
#define DDIM  128
#define H1DIM 64
#define H2DIM 32
#define NMAX  50000

// ---------------------------------------------------------------------------
// Scratch (static device globals — no runtime allocation allowed)
// ---------------------------------------------------------------------------
__device__ __nv_bfloat16 g_WcTh[2 * H1DIM * FDIM];  // folded W, transposed [half][n][k], hi split
__device__ __nv_bfloat16 g_WcTl[2 * H1DIM * FDIM];  // lo split
__device__ __nv_bfloat16 g_Wm2Th[H2DIM * H1DIM];    // Wm2 transposed [n=32][k=64], hi
__device__ __nv_bfloat16 g_Wm2Tl[H2DIM * H1DIM];    // lo
__device__ float g_bc1[H1DIM];
__device__ float g_bc2[H1DIM];
__device__ float g_g1[NMAX * H1DIM];    // x_gene @ Wc1 + bc1   [50000,64]
__device__ float g_g2[NMAX * H1DIM];    // x_cell @ Wc2 + bc2   [50000,64]

__device__ __forceinline__ uint32_t smem_u32(const void* p) {
    uint32_t a;
    asm("{ .reg .u64 t; cvta.to.shared.u64 t, %1; cvt.u32.u64 %0, t; }" : "=r"(a) : "l"(p));
    return a;
}

#define LDSM_X4(r, a) \
    asm volatile("ldmatrix.sync.aligned.m8n8.x4.shared.b16 {%0,%1,%2,%3}, [%4];" \
                 : "=r"((r)[0]), "=r"((r)[1]), "=r"((r)[2]), "=r"((r)[3]) : "r"(a))

#define MMA_BF16(c, a, b0, b1) \
    asm volatile("mma.sync.aligned.m16n8k16.row.col.f32.bf16.bf16.f32 " \
                 "{%0,%1,%2,%3}, {%4,%5,%6,%7}, {%8,%9}, {%0,%1,%2,%3};" \
                 : "+f"((c)[0]), "+f"((c)[1]), "+f"((c)[2]), "+f"((c)[3]) \
                 : "r"((a)[0]), "r"((a)[1]), "r"((a)[2]), "r"((a)[3]), "r"(b0), "r"(b1))

#define CP_ASYNC16(dst, src) \
    asm volatile("cp.async.ca.shared.global [%0], [%1], 16;" :: "r"(dst), "l"(src))
#define CP_COMMIT() asm volatile("cp.async.commit_group;" ::: "memory")
#define CP_WAIT1()  asm volatile("cp.async.wait_group 1;" ::: "memory")

__device__ __forceinline__ void split_bf16x2(float a, float b, uint32_t& hi, uint32_t& lo) {
    __nv_bfloat16 ha = __float2bfloat16(a);
    __nv_bfloat16 hb = __float2bfloat16(b);
    __nv_bfloat162 h = __halves2bfloat162(ha, hb);
    __nv_bfloat162 l = __floats2bfloat162_rn(a - __bfloat162float(ha),
                                             b - __bfloat162float(hb));
    hi = *(uint32_t*)&h;
    lo = *(uint32_t*)&l;
}

// ---------------------------------------------------------------------------
// Kernel 1: fold W{1,2} @ Wm1 halves -> transposed bf16 hi/lo. grid (1024,2) x 64
// ---------------------------------------------------------------------------
__global__ void fold_weights_kernel(const float* __restrict__ W1,
                                    const float* __restrict__ W2,
                                    const float* __restrict__ Wm1) {
    const int f    = blockIdx.x;
    const int half = blockIdx.y;
    const int j    = threadIdx.x;
    const float* W = half ? W2 : W1;
    const int off = half * DDIM;
    float acc = 0.f;
#pragma unroll 8
    for (int d = 0; d < DDIM; d++)
        acc = fmaf(W[f * DDIM + d], Wm1[(off + d) * H1DIM + j], acc);
    __nv_bfloat16 hi = __float2bfloat16(acc);
    __nv_bfloat16 lo = __float2bfloat16(acc - __bfloat162float(hi));
    const int idx = (half * H1DIM + j) * FDIM + f;
    g_WcTh[idx] = hi;
    g_WcTl[idx] = lo;
}

__global__ void fold_bias_kernel(const float* __restrict__ b1,
                                 const float* __restrict__ b2,
                                 const float* __restrict__ Wm1,
                                 const float* __restrict__ bm1) {
    const int t = threadIdx.x;
    if (t >= 128) return;
    const int j = t & 63;
    const int half = t >> 6;
    const float* b = half ? b2 : b1;
    const int off = half * DDIM;
    float acc = half ? 0.f : bm1[j];
#pragma unroll 8
    for (int d = 0; d < DDIM; d++)
        acc = fmaf(b[d], Wm1[(off + d) * H1DIM + j], acc);
    (half ? g_bc2 : g_bc1)[j] = acc;
}

// Kernel 1c: transpose+split Wm2 [64,32] -> [32][64] bf16 hi/lo. 1 block x 256
__global__ void fold_wm2_kernel(const float* __restrict__ Wm2) {
    for (int idx = threadIdx.x; idx < H2DIM * H1DIM; idx += 256) {
        const int n = idx & (H2DIM - 1);
        const int k = idx >> 5;
        float v = Wm2[k * H2DIM + n];
        __nv_bfloat16 hi = __float2bfloat16(v);
        __nv_bfloat16 lo = __float2bfloat16(v - __bfloat162float(hi));
        g_Wm2Th[n * H1DIM + k] = hi;
        g_Wm2Tl[n * H1DIM + k] = lo;
    }
}

// ---------------------------------------------------------------------------
// Kernel 2: mma.sync bf16-split projection GEMM  g = x @ Wc + bc
// BM=128, BN=64, BK=32, 256 threads. ONE barrier per chunk:
//   A 2-stage smem double buffer (STS for k+1 overlaps MMA on k)
//   B 3-stage cp.async ring (prefetch k+2 never collides with readers of k)
// Dynamic smem 71680B.
// ---------------------------------------------------------------------------
#define A_STRIDE   80
#define A_ST_BYTES (128 * A_STRIDE)          // 10240 per split per stage
#define B_ST_BYTES (H1DIM * B_STRIDE)        // 5120 per split per stage
#define B_STRIDE   80
// layout: A_hi[2] | A_lo[2] | B_hi[3] | B_lo[3]
#define OFF_A_HI   0
#define OFF_A_LO   (2 * A_ST_BYTES)          // 20480
#define OFF_B_HI   (4 * A_ST_BYTES)          // 40960
#define OFF_B_LO   (OFF_B_HI + 3 * B_ST_BYTES)  // 56320
#define SM_TOTAL   (OFF_B_LO + 3 * B_ST_BYTES)  // 71680

__global__ void __launch_bounds__(256)
proj_mma_kernel(const float* __restrict__ x_gene,
                const float* __restrict__ x_cell,
                int N1, int N2) {
    extern __shared__ __align__(16) char smem[];

    const int t   = threadIdx.x;
    const int wid = t >> 5;
    const int l   = t & 31;
    const int half = blockIdx.y;

    const float* x = half ? x_cell : x_gene;
    const char* WTh = (const char*)(g_WcTh + half * H1DIM * FDIM);
    const char* WTl = (const char*)(g_WcTl + half * H1DIM * FDIM);
    const float* bc = half ? g_bc2 : g_bc1;
    float* g = half ? g_g2 : g_g1;
    const int M  = half ? N2 : N1;
    const int m0 = blockIdx.x * 128;
    if (m0 >= M) return;

    const uint32_t sb = smem_u32(smem);

    const int m0w = (wid & 3) * 32;
    const int n0w = (wid >> 2) * 32;

    float acc[2][4][4] = {};

    const float4* xv = (const float4*)x;
    const int arow = t >> 3;           // 0..31
    const int ac4  = t & 7;
    const int brow = t >> 2;           // 0..63
    const int bq   = t & 3;

    size_t gmr[4];
#pragma unroll
    for (int r = 0; r < 4; r++) {
        int gm = m0 + arow + 32 * r;
        gmr[r] = (size_t)((gm < M) ? gm : (M - 1));
    }

    // LDSM offsets (relative to split-stage base)
    uint32_t a_off[2], b_off[2];
#pragma unroll
    for (int mt = 0; mt < 2; mt++)
        a_off[mt] = (uint32_t)((m0w + mt * 16 + (l & 15)) * A_STRIDE + (l >> 4) * 16);
#pragma unroll
    for (int gp = 0; gp < 2; gp++)
        b_off[gp] = (uint32_t)((n0w + gp * 16 + ((l >> 4) * 8) + (l & 7)) * B_STRIDE
                               + ((l >> 3) & 1) * 16);

    const size_t bgo = (size_t)brow * (FDIM * 2) + bq * 16;   // B gmem offset (bytes)
    const uint32_t bso = (uint32_t)(brow * B_STRIDE + bq * 16);
    const uint32_t a_sts = (uint32_t)(arow * A_STRIDE + ac4 * 8);

    // ---- Prologue ----
    float4 va[4];
#pragma unroll
    for (int r = 0; r < 4; r++) va[r] = xv[gmr[r] * (FDIM / 4) + ac4];     // chunk 0
    CP_ASYNC16(sb + OFF_B_HI + bso, WTh + bgo);                            // B chunk 0 -> stage 0
    CP_ASYNC16(sb + OFF_B_LO + bso, WTl + bgo);
    CP_COMMIT();
    CP_ASYNC16(sb + OFF_B_HI + B_ST_BYTES + bso, WTh + bgo + 64);          // B chunk 1 -> stage 1
    CP_ASYNC16(sb + OFF_B_LO + B_ST_BYTES + bso, WTl + bgo + 64);
    CP_COMMIT();
    // STS chunk 0 -> A stage 0
#pragma unroll
    for (int r = 0; r < 4; r++) {
        uint2 uh, ul;
        split_bf16x2(va[r].x, va[r].y, uh.x, ul.x);
        split_bf16x2(va[r].z, va[r].w, uh.y, ul.y);
        *(uint2*)(smem + OFF_A_HI + a_sts + 32 * r * A_STRIDE) = uh;
        *(uint2*)(smem + OFF_A_LO + a_sts + 32 * r * A_STRIDE) = ul;
    }
    // LDG chunk 1
#pragma unroll
    for (int r = 0; r < 4; r++) va[r] = xv[gmr[r] * (FDIM / 4) + 8 + ac4];
    CP_WAIT1();                       // B chunk 0 landed
    __syncthreads();

    int b_cur = 0;
    for (int kk = 0; kk < FDIM / 32; kk++) {
        const int a_cur = kk & 1;
        // 1. STS chunk kk+1 (in va) -> idle A stage
        if (kk < FDIM / 32 - 1) {
            const uint32_t abase = (uint32_t)((a_cur ^ 1) * A_ST_BYTES);
#pragma unroll
            for (int r = 0; r < 4; r++) {
                uint2 uh, ul;
                split_bf16x2(va[r].x, va[r].y, uh.x, ul.x);
                split_bf16x2(va[r].z, va[r].w, uh.y, ul.y);
                *(uint2*)(smem + OFF_A_HI + abase + a_sts + 32 * r * A_STRIDE) = uh;
                *(uint2*)(smem + OFF_A_LO + abase + a_sts + 32 * r * A_STRIDE) = ul;
            }
        }
        // 2. LDG chunk kk+2 (overlaps MMA)
        if (kk < FDIM / 32 - 2) {
#pragma unroll
            for (int r = 0; r < 4; r++)
                va[r] = xv[gmr[r] * (FDIM / 4) + (kk + 2) * 8 + ac4];
        }
        // 3. cp.async B chunk kk+2 -> ring stage (b_cur+2)%3
        if (kk < FDIM / 32 - 2) {
            int b2 = b_cur + 2; if (b2 >= 3) b2 -= 3;
            const uint32_t nb = (uint32_t)(b2 * B_ST_BYTES);
            CP_ASYNC16(sb + OFF_B_HI + nb + bso, WTh + bgo + (size_t)(kk + 2) * 64);
            CP_ASYNC16(sb + OFF_B_LO + nb + bso, WTl + bgo + (size_t)(kk + 2) * 64);
        }
        CP_COMMIT();                   // uniform group count (may be empty)

        // 4. MMA on A[a_cur], B[b_cur]
        const uint32_t ah_base = sb + OFF_A_HI + a_cur * A_ST_BYTES;
        const uint32_t al_base = sb + OFF_A_LO + a_cur * A_ST_BYTES;
        const uint32_t bh_base = sb + OFF_B_HI + b_cur * B_ST_BYTES;
        const uint32_t bl_base = sb + OFF_B_LO + b_cur * B_ST_BYTES;
#pragma unroll
        for (int kc = 0; kc < 2; kc++) {
            const uint32_t ko = kc * 32;
            uint32_t ah[2][4], al[2][4], bh[2][4], bl[2][4];
#pragma unroll
            for (int mt = 0; mt < 2; mt++) {
                LDSM_X4(ah[mt], ah_base + a_off[mt] + ko);
                LDSM_X4(al[mt], al_base + a_off[mt] + ko);
            }
#pragma unroll
            for (int gp = 0; gp < 2; gp++) {
                LDSM_X4(bh[gp], bh_base + b_off[gp] + ko);
                LDSM_X4(bl[gp], bl_base + b_off[gp] + ko);
            }
#pragma unroll
            for (int mt = 0; mt < 2; mt++) {
#pragma unroll
                for (int nt = 0; nt < 4; nt++) {
                    const int gp = nt >> 1;
                    const int br = (nt & 1) * 2;
                    MMA_BF16(acc[mt][nt], ah[mt], bh[gp][br], bh[gp][br + 1]);
                    MMA_BF16(acc[mt][nt], ah[mt], bl[gp][br], bl[gp][br + 1]);
                    MMA_BF16(acc[mt][nt], al[mt], bh[gp][br], bh[gp][br + 1]);
                }
            }
        }
        // 5. ensure chunk kk+1's B landed; 6. one barrier
        CP_WAIT1();
        __syncthreads();
        b_cur = (b_cur == 2) ? 0 : b_cur + 1;
    }

    // ---- Epilogue ----
#pragma unroll
    for (int mt = 0; mt < 2; mt++) {
#pragma unroll
        for (int nt = 0; nt < 4; nt++) {
            const int col = n0w + nt * 8 + 2 * (l & 3);
            const float bx = bc[col], by = bc[col + 1];
            const int r0 = m0 + m0w + mt * 16 + (l >> 2);
            if (r0 < M) {
                float2 o; o.x = acc[mt][nt][0] + bx; o.y = acc[mt][nt][1] + by;
                *(float2*)&g[(size_t)r0 * H1DIM + col] = o;
            }
            const int r1 = r0 + 8;
            if (r1 < M) {
                float2 o; o.x = acc[mt][nt][2] + bx; o.y = acc[mt][nt][3] + by;
                *(float2*)&g[(size_t)r1 * H1DIM + col] = o;
            }
        }
    }
}

// ---------------------------------------------------------------------------
// Kernel 3: edge stage, layer 2 via mma.sync (unchanged from R4 — passed).
// ---------------------------------------------------------------------------
#define EV_STRIDE 144   // 64 bf16 = 128B + 16B pad (conflict-free ldmatrix)

__global__ void __launch_bounds__(128)
edge_kernel(const int* __restrict__ eidx,
            const float* __restrict__ bm2,
            const float* __restrict__ Wm3,
            const float* __restrict__ bm3,
            float* __restrict__ out,
            int E, int N1, int N2) {
    __shared__ __align__(16) char vhi[128 * EV_STRIDE];
    __shared__ __align__(16) char vlo[128 * EV_STRIDE];
    __shared__ __align__(16) char wh[H2DIM * EV_STRIDE];
    __shared__ __align__(16) char wl[H2DIM * EV_STRIDE];
    __shared__ int ssh[128], dsh[128];

    const int t  = threadIdx.x;
    const int w  = t >> 5;
    const int l  = t & 31;
    const int e0 = blockIdx.x * 128;

    {
        int e = e0 + t;
        int s = 0, d = 0;
        if (e < E) {
            s = eidx[e];
            d = eidx[E + e];
            s = (s < 0) ? 0 : (s >= N1 ? N1 - 1 : s);
            d = (d < 0) ? 0 : (d >= N2 ? N2 - 1 : d);
        }
        ssh[t] = s;
        dsh[t] = d;
    }
    {
        const int row = t >> 2;
        const int q   = t & 3;
        const size_t go = (size_t)row * (H1DIM * 2) + q * 32;
        const uint32_t so = (uint32_t)(row * EV_STRIDE + q * 32);
        *(uint4*)(wh + so)      = *(const uint4*)((const char*)g_Wm2Th + go);
        *(uint4*)(wh + so + 16) = *(const uint4*)((const char*)g_Wm2Th + go + 16);
        *(uint4*)(wl + so)      = *(const uint4*)((const char*)g_Wm2Tl + go);
        *(uint4*)(wl + so + 16) = *(const uint4*)((const char*)g_Wm2Tl + go + 16);
    }
    __syncthreads();

    const float4* g1v = (const float4*)g_g1;
    const float4* g2v = (const float4*)g_g2;
#pragma unroll
    for (int it = 0; it < 16; it++) {
        const int i = t + it * 128;
        const int e = i >> 4;
        const int c = i & 15;
        float4 a = g1v[(size_t)ssh[e] * 16 + c];
        float4 b = g2v[(size_t)dsh[e] * 16 + c];
        float v0 = fmaxf(a.x + b.x, 0.f);
        float v1 = fmaxf(a.y + b.y, 0.f);
        float v2 = fmaxf(a.z + b.z, 0.f);
        float v3 = fmaxf(a.w + b.w, 0.f);
        uint2 uh, ul;
        split_bf16x2(v0, v1, uh.x, ul.x);
        split_bf16x2(v2, v3, uh.y, ul.y);
        const uint32_t off = (uint32_t)(e * EV_STRIDE + c * 8);
        *(uint2*)(vhi + off) = uh;
        *(uint2*)(vlo + off) = ul;
    }
    __syncthreads();

    const uint32_t vb_hi = smem_u32(vhi);
    const uint32_t vb_lo = smem_u32(vlo);
    const uint32_t wb_hi = smem_u32(wh);
    const uint32_t wb_lo = smem_u32(wl);

    uint32_t a_hi[2], a_lo[2], b_hi[2], b_lo[2];
#pragma unroll
    for (int mt = 0; mt < 2; mt++) {
        const uint32_t off = (uint32_t)((w * 32 + mt * 16 + (l & 15)) * EV_STRIDE + (l >> 4) * 16);
        a_hi[mt] = vb_hi + off;
        a_lo[mt] = vb_lo + off;
    }
#pragma unroll
    for (int gp = 0; gp < 2; gp++) {
        const uint32_t off = (uint32_t)((gp * 16 + ((l >> 4) * 8) + (l & 7)) * EV_STRIDE
                                        + ((l >> 3) & 1) * 16);
        b_hi[gp] = wb_hi + off;
        b_lo[gp] = wb_lo + off;
    }

    float acc[2][4][4] = {};
#pragma unroll
    for (int ks = 0; ks < 4; ks++) {
        const uint32_t ko = ks * 32;
        uint32_t ah[2][4], al[2][4], bh[2][4], bl[2][4];
#pragma unroll
        for (int mt = 0; mt < 2; mt++) {
            LDSM_X4(ah[mt], a_hi[mt] + ko);
            LDSM_X4(al[mt], a_lo[mt] + ko);
        }
#pragma unroll
        for (int gp = 0; gp < 2; gp++) {
            LDSM_X4(bh[gp], b_hi[gp] + ko);
            LDSM_X4(bl[gp], b_lo[gp] + ko);
        }
#pragma unroll
        for (int mt = 0; mt < 2; mt++) {
#pragma unroll
            for (int nt = 0; nt < 4; nt++) {
                const int gp = nt >> 1;
                const int br = (nt & 1) * 2;
                MMA_BF16(acc[mt][nt], ah[mt], bh[gp][br], bh[gp][br + 1]);
                MMA_BF16(acc[mt][nt], ah[mt], bl[gp][br], bl[gp][br + 1]);
                MMA_BF16(acc[mt][nt], al[mt], bh[gp][br], bh[gp][br + 1]);
            }
        }
    }

    float bm2v[4][2], wm3v[4][2];
#pragma unroll
    for (int nt = 0; nt < 4; nt++) {
        const int col = nt * 8 + 2 * (l & 3);
        bm2v[nt][0] = bm2[col];     bm2v[nt][1] = bm2[col + 1];
        wm3v[nt][0] = Wm3[col];     wm3v[nt][1] = Wm3[col + 1];
    }
    const float bm3v = bm3[0];

#pragma unroll
    for (int mt = 0; mt < 2; mt++) {
#pragma unroll
        for (int r = 0; r < 2; r++) {
            float s = 0.f;
#pragma unroll
            for (int nt = 0; nt < 4; nt++) {
                float c0 = fmaxf(acc[mt][nt][2 * r + 0] + bm2v[nt][0], 0.f);
                float c1 = fmaxf(acc[mt][nt][2 * r + 1] + bm2v[nt][1], 0.f);
                s = fmaf(c0, wm3v[nt][0], s);
                s = fmaf(c1, wm3v[nt][1], s);
            }
            s += __shfl_xor_sync(0xffffffffu, s, 1);
            s += __shfl_xor_sync(0xffffffffu, s, 2);
            if ((l & 3) == 0) {
                const int ge = e0 + w * 32 + mt * 16 + r * 8 + (l >> 2);
                if (ge < E) out[ge] = s + bm3v;
            }
        }
    }
}

// ---------------------------------------------------------------------------
extern "C" void kernel_launch(void* const* d_in, const int* in_sizes, int n_in,
                              void* d_out, int out_size) {
    const float* x_gene = (const float*)d_in[0];
    const float* x_cell = (const float*)d_in[1];
    const int*   eidx   = (const int*)  d_in[2];
    const float* W1     = (const float*)d_in[3];
    const float* b1     = (const float*)d_in[4];
    const float* W2     = (const float*)d_in[5];
    const float* b2     = (const float*)d_in[6];
    const float* Wm1    = (const float*)d_in[7];
    const float* bm1    = (const float*)d_in[8];
    const float* Wm2    = (const float*)d_in[9];
    const float* bm2    = (const float*)d_in[10];
    const float* Wm3    = (const float*)d_in[11];
    const float* bm3    = (const float*)d_in[12];
    float* out = (float*)d_out;

    const int N1 = in_sizes[0] / FDIM;
    const int N2 = in_sizes[1] / FDIM;
    const int E  = in_sizes[2] / 2;

    // Host-side attribute set (not an allocation; idempotent; capture-safe)
    cudaFuncSetAttribute(proj_mma_kernel,
                         cudaFuncAttributeMaxDynamicSharedMemorySize, SM_TOTAL);

    fold_weights_kernel<<<dim3(FDIM, 2), H1DIM>>>(W1, W2, Wm1);
    fold_bias_kernel<<<1, 128>>>(b1, b2, Wm1, bm1);
    fold_wm2_kernel<<<1, 256>>>(Wm2);

    const int Mmax = (N1 > N2) ? N1 : N2;
    proj_mma_kernel<<<dim3((Mmax + 127) / 128, 2), 256, SM_TOTAL>>>(x_gene, x_cell, N1, N2);

    edge_kernel<<<(E + 127) / 128, 128>>>(eidx, bm2, Wm3, bm3, out, E, N1, N2);
}

// round 6
// speedup vs baseline: 2.8247x; 1.1876x over previous
#include <cuda_runtime.h>
#include <cuda_bf16.h>
#include <cstdint>

// Problem constants (fixed by dataset: N1=N2=50000, F=1024, D=128, H1=64, H2=32, E=1e6)
#define FDIM  1024
#define DDIM  128
#define H1DIM 64
#define H2DIM 32
#define NMAX  50000

// ---------------------------------------------------------------------------
// Scratch (static device globals — no runtime allocation allowed)
// ---------------------------------------------------------------------------
__device__ __nv_bfloat16 g_WcTh[2 * H1DIM * FDIM];  // folded W, transposed [half][n][k], hi split
__device__ __nv_bfloat16 g_WcTl[2 * H1DIM * FDIM];  // lo split
__device__ __align__(16) unsigned char g_Wm2F[8192]; // Wm2 bf16 hi/lo in mma-fragment lane order
__device__ float g_bc1[H1DIM];
__device__ float g_bc2[H1DIM];
__device__ float g_g1[NMAX * H1DIM];    // x_gene @ Wc1 + bc1   [50000,64]
__device__ float g_g2[NMAX * H1DIM];    // x_cell @ Wc2 + bc2   [50000,64]

__device__ __forceinline__ uint32_t smem_u32(const void* p) {
    uint32_t a;
    asm("{ .reg .u64 t; cvta.to.shared.u64 t, %1; cvt.u32.u64 %0, t; }" : "=r"(a) : "l"(p));
    return a;
}

#define LDSM_X4(r, a) \
    asm volatile("ldmatrix.sync.aligned.m8n8.x4.shared.b16 {%0,%1,%2,%3}, [%4];" \
                 : "=r"((r)[0]), "=r"((r)[1]), "=r"((r)[2]), "=r"((r)[3]) : "r"(a))

#define MMA_BF16(c, a, b0, b1) \
    asm volatile("mma.sync.aligned.m16n8k16.row.col.f32.bf16.bf16.f32 " \
                 "{%0,%1,%2,%3}, {%4,%5,%6,%7}, {%8,%9}, {%0,%1,%2,%3};" \
                 : "+f"((c)[0]), "+f"((c)[1]), "+f"((c)[2]), "+f"((c)[3]) \
                 : "r"((a)[0]), "r"((a)[1]), "r"((a)[2]), "r"((a)[3]), "r"(b0), "r"(b1))

#define CP_ASYNC16(dst, src) \
    asm volatile("cp.async.ca.shared.global [%0], [%1], 16;" :: "r"(dst), "l"(src))
#define CP_COMMIT() asm volatile("cp.async.commit_group;" ::: "memory")
#define CP_WAIT1()  asm volatile("cp.async.wait_group 1;" ::: "memory")

__device__ __forceinline__ void split_bf16x2(float a, float b, uint32_t& hi, uint32_t& lo) {
    __nv_bfloat16 ha = __float2bfloat16(a);
    __nv_bfloat16 hb = __float2bfloat16(b);
    __nv_bfloat162 h = __halves2bfloat162(ha, hb);
    __nv_bfloat162 l = __floats2bfloat162_rn(a - __bfloat162float(ha),
                                             b - __bfloat162float(hb));
    hi = *(uint32_t*)&h;
    lo = *(uint32_t*)&l;
}

// ---------------------------------------------------------------------------
// Kernel 1: fold W{1,2} @ Wm1 halves -> transposed bf16 hi/lo. grid (1024,2) x 64
// ---------------------------------------------------------------------------
__global__ void fold_weights_kernel(const float* __restrict__ W1,
                                    const float* __restrict__ W2,
                                    const float* __restrict__ Wm1) {
    const int f    = blockIdx.x;
    const int half = blockIdx.y;
    const int j    = threadIdx.x;
    const float* W = half ? W2 : W1;
    const int off = half * DDIM;
    float acc = 0.f;
#pragma unroll 8
    for (int d = 0; d < DDIM; d++)
        acc = fmaf(W[f * DDIM + d], Wm1[(off + d) * H1DIM + j], acc);
    __nv_bfloat16 hi = __float2bfloat16(acc);
    __nv_bfloat16 lo = __float2bfloat16(acc - __bfloat162float(hi));
    const int idx = (half * H1DIM + j) * FDIM + f;
    g_WcTh[idx] = hi;
    g_WcTl[idx] = lo;
}

__global__ void fold_bias_kernel(const float* __restrict__ b1,
                                 const float* __restrict__ b2,
                                 const float* __restrict__ Wm1,
                                 const float* __restrict__ bm1) {
    const int t = threadIdx.x;
    if (t >= 128) return;
    const int j = t & 63;
    const int half = t >> 6;
    const float* b = half ? b2 : b1;
    const int off = half * DDIM;
    float acc = half ? 0.f : bm1[j];
#pragma unroll 8
    for (int d = 0; d < DDIM; d++)
        acc = fmaf(b[d], Wm1[(off + d) * H1DIM + j], acc);
    (half ? g_bc2 : g_bc1)[j] = acc;
}

// Kernel 1c: Wm2 [64,32] -> bf16 hi/lo in mma-FRAGMENT lane order.
// Frag addr for (n,k,split s): ks=k>>4, G=n>>4, rr=n&7, mh=(n>>3)&1, kb=k&15,
//   lane = rr*4 + ((kb&7)>>1), reg = mh*2 + (kb>>3)
//   byte = (((ks*2+G)*2+s)*512) + lane*16 + reg*4 + (kb&1)*2
__global__ void fold_wm2_kernel(const float* __restrict__ Wm2) {
    for (int idx = threadIdx.x; idx < H2DIM * H1DIM; idx += 256) {
        const int n = idx & (H2DIM - 1);
        const int k = idx >> 5;            // 0..63
        float v = Wm2[k * H2DIM + n];
        __nv_bfloat16 hi = __float2bfloat16(v);
        __nv_bfloat16 lo = __float2bfloat16(v - __bfloat162float(hi));
        const int ks = k >> 4, G = n >> 4, rr = n & 7, mh = (n >> 3) & 1, kb = k & 15;
        const int lane = rr * 4 + ((kb & 7) >> 1);
        const int reg  = mh * 2 + (kb >> 3);
        const int base = ((ks * 2 + G) * 2) * 512 + lane * 16 + reg * 4 + (kb & 1) * 2;
        *(__nv_bfloat16*)(g_Wm2F + base)       = hi;   // s = 0
        *(__nv_bfloat16*)(g_Wm2F + base + 512) = lo;   // s = 1
    }
}

// ---------------------------------------------------------------------------
// Kernel 2: mma.sync bf16-split projection GEMM (UNCHANGED from R5 — isolate edge change)
// ---------------------------------------------------------------------------
#define A_STRIDE   80
#define A_ST_BYTES (128 * A_STRIDE)
#define B_STRIDE   80
#define B_ST_BYTES (H1DIM * B_STRIDE)
#define OFF_A_HI   0
#define OFF_A_LO   (2 * A_ST_BYTES)
#define OFF_B_HI   (4 * A_ST_BYTES)
#define OFF_B_LO   (OFF_B_HI + 3 * B_ST_BYTES)
#define SM_TOTAL   (OFF_B_LO + 3 * B_ST_BYTES)

__global__ void __launch_bounds__(256)
proj_mma_kernel(const float* __restrict__ x_gene,
                const float* __restrict__ x_cell,
                int N1, int N2) {
    extern __shared__ __align__(16) char smem[];

    const int t   = threadIdx.x;
    const int wid = t >> 5;
    const int l   = t & 31;
    const int half = blockIdx.y;

    const float* x = half ? x_cell : x_gene;
    const char* WTh = (const char*)(g_WcTh + half * H1DIM * FDIM);
    const char* WTl = (const char*)(g_WcTl + half * H1DIM * FDIM);
    const float* bc = half ? g_bc2 : g_bc1;
    float* g = half ? g_g2 : g_g1;
    const int M  = half ? N2 : N1;
    const int m0 = blockIdx.x * 128;
    if (m0 >= M) return;

    const uint32_t sb = smem_u32(smem);

    const int m0w = (wid & 3) * 32;
    const int n0w = (wid >> 2) * 32;

    float acc[2][4][4] = {};

    const float4* xv = (const float4*)x;
    const int arow = t >> 3;
    const int ac4  = t & 7;
    const int brow = t >> 2;
    const int bq   = t & 3;

    size_t gmr[4];
#pragma unroll
    for (int r = 0; r < 4; r++) {
        int gm = m0 + arow + 32 * r;
        gmr[r] = (size_t)((gm < M) ? gm : (M - 1));
    }

    uint32_t a_off[2], b_off[2];
#pragma unroll
    for (int mt = 0; mt < 2; mt++)
        a_off[mt] = (uint32_t)((m0w + mt * 16 + (l & 15)) * A_STRIDE + (l >> 4) * 16);
#pragma unroll
    for (int gp = 0; gp < 2; gp++)
        b_off[gp] = (uint32_t)((n0w + gp * 16 + ((l >> 4) * 8) + (l & 7)) * B_STRIDE
                               + ((l >> 3) & 1) * 16);

    const size_t bgo = (size_t)brow * (FDIM * 2) + bq * 16;
    const uint32_t bso = (uint32_t)(brow * B_STRIDE + bq * 16);
    const uint32_t a_sts = (uint32_t)(arow * A_STRIDE + ac4 * 8);

    float4 va[4];
#pragma unroll
    for (int r = 0; r < 4; r++) va[r] = xv[gmr[r] * (FDIM / 4) + ac4];
    CP_ASYNC16(sb + OFF_B_HI + bso, WTh + bgo);
    CP_ASYNC16(sb + OFF_B_LO + bso, WTl + bgo);
    CP_COMMIT();
    CP_ASYNC16(sb + OFF_B_HI + B_ST_BYTES + bso, WTh + bgo + 64);
    CP_ASYNC16(sb + OFF_B_LO + B_ST_BYTES + bso, WTl + bgo + 64);
    CP_COMMIT();
#pragma unroll
    for (int r = 0; r < 4; r++) {
        uint2 uh, ul;
        split_bf16x2(va[r].x, va[r].y, uh.x, ul.x);
        split_bf16x2(va[r].z, va[r].w, uh.y, ul.y);
        *(uint2*)(smem + OFF_A_HI + a_sts + 32 * r * A_STRIDE) = uh;
        *(uint2*)(smem + OFF_A_LO + a_sts + 32 * r * A_STRIDE) = ul;
    }
#pragma unroll
    for (int r = 0; r < 4; r++) va[r] = xv[gmr[r] * (FDIM / 4) + 8 + ac4];
    CP_WAIT1();
    __syncthreads();

    int b_cur = 0;
    for (int kk = 0; kk < FDIM / 32; kk++) {
        const int a_cur = kk & 1;
        if (kk < FDIM / 32 - 1) {
            const uint32_t abase = (uint32_t)((a_cur ^ 1) * A_ST_BYTES);
#pragma unroll
            for (int r = 0; r < 4; r++) {
                uint2 uh, ul;
                split_bf16x2(va[r].x, va[r].y, uh.x, ul.x);
                split_bf16x2(va[r].z, va[r].w, uh.y, ul.y);
                *(uint2*)(smem + OFF_A_HI + abase + a_sts + 32 * r * A_STRIDE) = uh;
                *(uint2*)(smem + OFF_A_LO + abase + a_sts + 32 * r * A_STRIDE) = ul;
            }
        }
        if (kk < FDIM / 32 - 2) {
#pragma unroll
            for (int r = 0; r < 4; r++)
                va[r] = xv[gmr[r] * (FDIM / 4) + (kk + 2) * 8 + ac4];
        }
        if (kk < FDIM / 32 - 2) {
            int b2 = b_cur + 2; if (b2 >= 3) b2 -= 3;
            const uint32_t nb = (uint32_t)(b2 * B_ST_BYTES);
            CP_ASYNC16(sb + OFF_B_HI + nb + bso, WTh + bgo + (size_t)(kk + 2) * 64);
            CP_ASYNC16(sb + OFF_B_LO + nb + bso, WTl + bgo + (size_t)(kk + 2) * 64);
        }
        CP_COMMIT();

        const uint32_t ah_base = sb + OFF_A_HI + a_cur * A_ST_BYTES;
        const uint32_t al_base = sb + OFF_A_LO + a_cur * A_ST_BYTES;
        const uint32_t bh_base = sb + OFF_B_HI + b_cur * B_ST_BYTES;
        const uint32_t bl_base = sb + OFF_B_LO + b_cur * B_ST_BYTES;
#pragma unroll
        for (int kc = 0; kc < 2; kc++) {
            const uint32_t ko = kc * 32;
            uint32_t ah[2][4], al[2][4], bh[2][4], bl[2][4];
#pragma unroll
            for (int mt = 0; mt < 2; mt++) {
                LDSM_X4(ah[mt], ah_base + a_off[mt] + ko);
                LDSM_X4(al[mt], al_base + a_off[mt] + ko);
            }
#pragma unroll
            for (int gp = 0; gp < 2; gp++) {
                LDSM_X4(bh[gp], bh_base + b_off[gp] + ko);
                LDSM_X4(bl[gp], bl_base + b_off[gp] + ko);
            }
#pragma unroll
            for (int mt = 0; mt < 2; mt++) {
#pragma unroll
                for (int nt = 0; nt < 4; nt++) {
                    const int gp = nt >> 1;
                    const int br = (nt & 1) * 2;
                    MMA_BF16(acc[mt][nt], ah[mt], bh[gp][br], bh[gp][br + 1]);
                    MMA_BF16(acc[mt][nt], ah[mt], bl[gp][br], bl[gp][br + 1]);
                    MMA_BF16(acc[mt][nt], al[mt], bh[gp][br], bh[gp][br + 1]);
                }
            }
        }
        CP_WAIT1();
        __syncthreads();
        b_cur = (b_cur == 2) ? 0 : b_cur + 1;
    }

#pragma unroll
    for (int mt = 0; mt < 2; mt++) {
#pragma unroll
        for (int nt = 0; nt < 4; nt++) {
            const int col = n0w + nt * 8 + 2 * (l & 3);
            const float bx = bc[col], by = bc[col + 1];
            const int r0 = m0 + m0w + mt * 16 + (l >> 2);
            if (r0 < M) {
                float2 o; o.x = acc[mt][nt][0] + bx; o.y = acc[mt][nt][1] + by;
                *(float2*)&g[(size_t)r0 * H1DIM + col] = o;
            }
            const int r1 = r0 + 8;
            if (r1 < M) {
                float2 o; o.x = acc[mt][nt][2] + bx; o.y = acc[mt][nt][3] + by;
                *(float2*)&g[(size_t)r1 * H1DIM + col] = o;
            }
        }
    }
}

// ---------------------------------------------------------------------------
// Kernel 3: BARRIER-FREE edge stage.
// Each warp owns 32 edges end-to-end: gathers its own A rows (so no block
// barrier between gather and MMA), indices via __shfl, Wm2 fragments via
// LDG.128 from the 8KB L1-resident frag table (no weight smem, no init sync).
// smem = 36.9KB -> 6 CTAs/SM.
// ---------------------------------------------------------------------------
#define EV_STRIDE 144   // 64 bf16 = 128B + 16B pad (conflict-free ldmatrix)

__global__ void __launch_bounds__(128)
edge_kernel(const int* __restrict__ eidx,
            const float* __restrict__ bm2,
            const float* __restrict__ Wm3,
            const float* __restrict__ bm3,
            float* __restrict__ out,
            int E, int N1, int N2) {
    __shared__ __align__(16) char vhi[128 * EV_STRIDE];
    __shared__ __align__(16) char vlo[128 * EV_STRIDE];

    const int t  = threadIdx.x;
    const int w  = t >> 5;
    const int l  = t & 31;
    const int e0 = blockIdx.x * 128;

    // Each lane loads + clamps the indices of its own edge (warp-local 32 edges)
    int s_l, d_l;
    {
        int eg = e0 + w * 32 + l;
        int ec = (eg < E) ? eg : (E - 1);
        int s = eidx[ec];
        int d = eidx[E + ec];
        s_l = (s < 0) ? 0 : (s >= N1 ? N1 - 1 : s);
        d_l = (d < 0) ? 0 : (d >= N2 ? N2 - 1 : d);
    }

    // Gather + add + relu -> bf16 hi/lo, into this warp's own 32-row region
    const float4* g1v = (const float4*)g_g1;
    const float4* g2v = (const float4*)g_g2;
    const int c = l & 15;
#pragma unroll
    for (int it = 0; it < 16; it++) {
        const int e = (l >> 4) + 2 * it;               // 0..31 local edge
        const int si = __shfl_sync(0xffffffffu, s_l, e);
        const int di = __shfl_sync(0xffffffffu, d_l, e);
        float4 a = g1v[si * 16 + c];
        float4 b = g2v[di * 16 + c];
        float v0 = fmaxf(a.x + b.x, 0.f);
        float v1 = fmaxf(a.y + b.y, 0.f);
        float v2 = fmaxf(a.z + b.z, 0.f);
        float v3 = fmaxf(a.w + b.w, 0.f);
        uint2 uh, ul;
        split_bf16x2(v0, v1, uh.x, ul.x);
        split_bf16x2(v2, v3, uh.y, ul.y);
        const uint32_t off = (uint32_t)((w * 32 + e) * EV_STRIDE + c * 8);
        *(uint2*)(vhi + off) = uh;
        *(uint2*)(vlo + off) = ul;
    }
    __syncwarp();

    // MMA: v[32,64] @ Wm2T[32,64]^T, bf16 hi/lo 3-product, fp32 acc
    const uint32_t vb_hi = smem_u32(vhi);
    const uint32_t vb_lo = smem_u32(vlo);
    uint32_t a_hi[2], a_lo[2];
#pragma unroll
    for (int mt = 0; mt < 2; mt++) {
        const uint32_t off = (uint32_t)((w * 32 + mt * 16 + (l & 15)) * EV_STRIDE + (l >> 4) * 16);
        a_hi[mt] = vb_hi + off;
        a_lo[mt] = vb_lo + off;
    }

    float acc[2][4][4] = {};
#pragma unroll
    for (int ks = 0; ks < 4; ks++) {
        // B fragments straight from gmem frag table (L1-hot, identical across CTAs)
        uint32_t bh[2][4], bl[2][4];
#pragma unroll
        for (int G = 0; G < 2; G++) {
            *(uint4*)bh[G] = *(const uint4*)(g_Wm2F + ((ks * 2 + G) * 2 + 0) * 512 + l * 16);
            *(uint4*)bl[G] = *(const uint4*)(g_Wm2F + ((ks * 2 + G) * 2 + 1) * 512 + l * 16);
        }
        const uint32_t ko = ks * 32;
        uint32_t ah[2][4], al[2][4];
#pragma unroll
        for (int mt = 0; mt < 2; mt++) {
            LDSM_X4(ah[mt], a_hi[mt] + ko);
            LDSM_X4(al[mt], a_lo[mt] + ko);
        }
#pragma unroll
        for (int mt = 0; mt < 2; mt++) {
#pragma unroll
            for (int nt = 0; nt < 4; nt++) {
                const int gp = nt >> 1;
                const int br = (nt & 1) * 2;
                MMA_BF16(acc[mt][nt], ah[mt], bh[gp][br], bh[gp][br + 1]);
                MMA_BF16(acc[mt][nt], ah[mt], bl[gp][br], bl[gp][br + 1]);
                MMA_BF16(acc[mt][nt], al[mt], bh[gp][br], bh[gp][br + 1]);
            }
        }
    }

    // Epilogue: u = relu(acc + bm2), partial = u * Wm3, quad-reduce over N=32
    float bm2v[4][2], wm3v[4][2];
#pragma unroll
    for (int nt = 0; nt < 4; nt++) {
        const int col = nt * 8 + 2 * (l & 3);
        bm2v[nt][0] = bm2[col];     bm2v[nt][1] = bm2[col + 1];
        wm3v[nt][0] = Wm3[col];     wm3v[nt][1] = Wm3[col + 1];
    }
    const float bm3v = bm3[0];

#pragma unroll
    for (int mt = 0; mt < 2; mt++) {
#pragma unroll
        for (int r = 0; r < 2; r++) {
            float s = 0.f;
#pragma unroll
            for (int nt = 0; nt < 4; nt++) {
                float c0 = fmaxf(acc[mt][nt][2 * r + 0] + bm2v[nt][0], 0.f);
                float c1 = fmaxf(acc[mt][nt][2 * r + 1] + bm2v[nt][1], 0.f);
                s = fmaf(c0, wm3v[nt][0], s);
                s = fmaf(c1, wm3v[nt][1], s);
            }
            s += __shfl_xor_sync(0xffffffffu, s, 1);
            s += __shfl_xor_sync(0xffffffffu, s, 2);
            if ((l & 3) == 0) {
                const int ge = e0 + w * 32 + mt * 16 + r * 8 + (l >> 2);
                if (ge < E) out[ge] = s + bm3v;
            }
        }
    }
}

// ---------------------------------------------------------------------------
extern "C" void kernel_launch(void* const* d_in, const int* in_sizes, int n_in,
                              void* d_out, int out_size) {
    const float* x_gene = (const float*)d_in[0];
    const float* x_cell = (const float*)d_in[1];
    const int*   eidx   = (const int*)  d_in[2];
    const float* W1     = (const float*)d_in[3];
    const float* b1     = (const float*)d_in[4];
    const float* W2     = (const float*)d_in[5];
    const float* b2     = (const float*)d_in[6];
    const float* Wm1    = (const float*)d_in[7];
    const float* bm1    = (const float*)d_in[8];
    const float* Wm2    = (const float*)d_in[9];
    const float* bm2    = (const float*)d_in[10];
    const float* Wm3    = (const float*)d_in[11];
    const float* bm3    = (const float*)d_in[12];
    float* out = (float*)d_out;

    const int N1 = in_sizes[0] / FDIM;
    const int N2 = in_sizes[1] / FDIM;
    const int E  = in_sizes[2] / 2;

    cudaFuncSetAttribute(proj_mma_kernel,
                         cudaFuncAttributeMaxDynamicSharedMemorySize, SM_TOTAL);

    fold_weights_kernel<<<dim3(FDIM, 2), H1DIM>>>(W1, W2, Wm1);
    fold_bias_kernel<<<1, 128>>>(b1, b2, Wm1, bm1);
    fold_wm2_kernel<<<1, 256>>>(Wm2);

    const int Mmax = (N1 > N2) ? N1 : N2;
    proj_mma_kernel<<<dim3((Mmax + 127) / 128, 2), 256, SM_TOTAL>>>(x_gene, x_cell, N1, N2);

    edge_kernel<<<(E + 127) / 128, 128>>>(eidx, bm2, Wm3, bm3, out, E, N1, N2);
}